// round 15
// baseline (speedup 1.0000x reference)
#include <cuda_runtime.h>
#include <cuda_bf16.h>
#include <cstdint>

#define B 8
#define N 65536
#define C 256
#define NS 1024
#define K1 259              // real K of layer 1 (3 xyz + 256 feat)
#define KP 288              // padded K (multiple of KT=32!)
#define M 128
#define MH 64               // M per block
#define NT 64
#define KT 32
#define EPS 1e-5f
#define CH 2048             // ballquery chunk (points)

// ---------------- scratch (device globals; no allocs) ---------------------
__device__ __align__(256) int      d_inds[B][NS];
__device__ __align__(256) float    d_g [B][KP][NS];   // rows 0-2 xyz, 3-258 feat, 259+ zero
__device__ __align__(256) float    d_y1[B][M][NS];
__device__ __align__(256) float    d_y2[B][M][NS];
__device__ __align__(256) float    d_wT1[KP][M];      // rows >= K1 zero
__device__ __align__(256) float    d_wT2[M][M];
__device__ __align__(256) float    d_wT3[M][M];
__device__ __align__(256) float    d_hT1[M][M];
__device__ __align__(256) float    d_hT2[M][M];
__device__ __align__(256) float    d_sum [3][M];
__device__ __align__(256) float    d_sum2[3][M];
__device__ __align__(256) unsigned d_maxenc[B][M];
__device__ __align__(256) unsigned d_minenc[B][M];

__device__ __forceinline__ unsigned enc(float f) {
    unsigned u = __float_as_uint(f);
    return (u & 0x80000000u) ? ~u : (u | 0x80000000u);
}
__device__ __forceinline__ float dec(unsigned u) {
    return __uint_as_float((u & 0x80000000u) ? (u ^ 0x80000000u) : ~u);
}

// ---- packed fp32x2 helpers (sm_103a; bit-exact dual FMA) ------------------
__device__ __forceinline__ unsigned long long pk2(float lo, float hi) {
    unsigned long long o;
    asm("mov.b64 %0, {%1, %2};" : "=l"(o) : "f"(lo), "f"(hi));
    return o;
}
#define FFMA2(d, a, b) \
    asm("fma.rn.f32x2 %0, %1, %2, %3;" : "=l"(d) : "l"(a), "l"(b), "l"(d))
__device__ __forceinline__ void unpk2(unsigned long long v, float& lo, float& hi) {
    asm("mov.b64 {%0, %1}, %2;" : "=f"(lo), "=f"(hi) : "l"(v));
}

// ---------- 0) setup: ballquery only (8 blocks, coalesced chunks) ----------
__global__ void __launch_bounds__(256)
setup_kernel(const float* __restrict__ xyz) {
    int b = blockIdx.x;
    int tid = threadIdx.x;
    const float* x = xyz + (size_t)b * N * 3;
    float cx = x[0], cy = x[1], cz = x[2];
    int lane = tid & 31, warp = tid >> 5;

    __shared__ float4 s_stage[CH * 3 / 4];   // 24KB
    __shared__ int s_wsum[8];
    __shared__ int s_base;
    if (tid == 0) s_base = 0;
    __syncthreads();

    const float* sp = (const float*)s_stage;
    for (int c0 = 0; c0 < N; c0 += CH) {
        const float4* src = (const float4*)(x + (size_t)c0 * 3);
        #pragma unroll
        for (int j = 0; j < 6; j++)
            s_stage[tid + 256 * j] = src[tid + 256 * j];
        int base = s_base;
        __syncthreads();

        unsigned msk = 0; int cnt = 0;
        #pragma unroll
        for (int j = 0; j < 8; j++) {
            int p = tid * 8 + j;
            float dx = sp[p*3+0] - cx;
            float dy = sp[p*3+1] - cy;
            float dz = sp[p*3+2] - cz;
            if (dx*dx + dy*dy + dz*dz < 1.0f) { msk |= (1u << j); cnt++; }
        }
        int incl = cnt;
        #pragma unroll
        for (int o = 1; o < 32; o <<= 1) {
            int t2 = __shfl_up_sync(0xffffffffu, incl, o);
            if (lane >= o) incl += t2;
        }
        if (lane == 31) s_wsum[warp] = incl;
        __syncthreads();
        if (tid < 8) {
            int v = s_wsum[tid];
            #pragma unroll
            for (int o = 1; o < 8; o <<= 1) {
                int t2 = __shfl_up_sync(0xffu, v, o);
                if (tid >= o) v += t2;
            }
            s_wsum[tid] = v;
        }
        __syncthreads();
        int excl = incl - cnt + (warp ? s_wsum[warp - 1] : 0);
        int total = s_wsum[7];

        int pos = base + excl;
        unsigned m = msk;
        while (m && pos < NS) {
            int j = __ffs(m) - 1;
            d_inds[b][pos++] = c0 + tid * 8 + j;
            m &= (m - 1);
        }
        __syncthreads();
        if (tid == 0) s_base = base + total;
        if (base + total >= NS) { __syncthreads(); break; }
        __syncthreads();
    }

    __syncthreads();
    int count = min(s_base, NS);
    for (int p = count + tid; p < NS; p += 256) d_inds[b][p] = 0;
    __syncthreads();

    for (int n = tid; n < NS; n += 256) {
        int id = d_inds[b][n];
        d_g[b][0][n] = x[id*3+0] - cx;
        d_g[b][1][n] = x[id*3+1] - cy;
        d_g[b][2][n] = x[id*3+2] - cz;
    }
}

// -------- 1) gather (x<C) + concurrent weight-prep (x>=C) ------------------
__global__ void __launch_bounds__(128)
gather_kernel(const float* __restrict__ feat,
              const float* __restrict__ w1,
              const float* __restrict__ w2,
              const float* __restrict__ w3,
              const float* __restrict__ hw1,
              const float* __restrict__ hw2) {
    int cx = blockIdx.x;
    int b  = blockIdx.y;
    int tid = threadIdx.x;              // 128

    if (cx >= C) {
        // prep slice: 16 blocks x 128 thr, runs concurrent with gather
        int gtid = ((cx - C) * B + b) * 128 + tid;
        int nthr = 2 * B * 128;
        for (int i = gtid; i < 3 * M; i += nthr) { (&d_sum[0][0])[i] = 0.f; (&d_sum2[0][0])[i] = 0.f; }
        for (int i = gtid; i < B * M; i += nthr) { (&d_maxenc[0][0])[i] = 0u; (&d_minenc[0][0])[i] = 0xFFFFFFFFu; }
        // zero d_g padding rows (k = K1..KP-1)
        for (int i = gtid; i < B * (KP - K1) * NS; i += nthr) {
            int bb = i / ((KP - K1) * NS);
            int r = i % ((KP - K1) * NS);
            d_g[bb][K1 + r / NS][r % NS] = 0.f;
        }
        // w1 transpose with zero-padded rows (coalesced source reads)
        for (int i = gtid; i < M * KP; i += nthr) {
            int m = i / KP, k = i % KP;
            d_wT1[k][m] = (k < K1) ? w1[m * K1 + k] : 0.f;
        }
        for (int i = gtid; i < M * M; i += nthr) {
            int m = i >> 7, k = i & 127;
            d_wT2[k][m] = w2[m * M + k];
            d_wT3[k][m] = w3[m * M + k];
            d_hT1[k][m] = hw1[m * M + k];
            d_hT2[k][m] = hw2[m * M + k];
        }
        return;
    }

    const float* fp = feat + ((size_t)b * C + cx) * N;
    int n = tid * 8;
    int4 i0 = *(const int4*)&d_inds[b][n];
    int4 i1 = *(const int4*)&d_inds[b][n + 4];
    float4 v0, v1;
    v0.x = __ldg(fp + i0.x); v0.y = __ldg(fp + i0.y);
    v0.z = __ldg(fp + i0.z); v0.w = __ldg(fp + i0.w);
    v1.x = __ldg(fp + i1.x); v1.y = __ldg(fp + i1.y);
    v1.z = __ldg(fp + i1.z); v1.w = __ldg(fp + i1.w);
    *(float4*)&d_g[b][3 + cx][n]     = v0;
    *(float4*)&d_g[b][3 + cx][n + 4] = v1;
}

// ---------------- 2) fused GEMM (fp32x2, KT=32) + BN-prev + stats ----------
template<int K, int LAYER>
__global__ void __launch_bounds__(256)
gemm_kernel(const float* __restrict__ bias,
            const float* __restrict__ gamma_prev,
            const float* __restrict__ beta_prev) {
    __shared__ float As[KT][MH];         // 8KB
    __shared__ float Bs[KT][NT];         // 8KB
    __shared__ float red [16][MH + 1];
    __shared__ float red2[16][MH + 1];
    __shared__ float s_scale[M], s_shift[M];

    int n0 = blockIdx.x * NT;
    int m0 = blockIdx.y * MH;
    int b  = blockIdx.z;
    int tid = threadIdx.x;               // 256
    int tm = (tid & 15) * 4;
    int tn = (tid >> 4) * 4;
    int g  = tid >> 4;

    if (LAYER > 0) {
        if (tid < M) {
            float inv = 1.0f / (float)(B * NS);
            float mn  = d_sum [LAYER-1][tid] * inv;
            float var = d_sum2[LAYER-1][tid] * inv - mn * mn;
            float a = gamma_prev[tid] * rsqrtf(var + EPS);
            s_scale[tid] = a;
            s_shift[tid] = beta_prev[tid] - mn * a;
        }
        __syncthreads();
    }

    unsigned long long acc2[4][2] = {};
    const float* Wt = (LAYER == 0) ? &d_wT1[0][0] : (LAYER == 1 ? &d_wT2[0][0] : &d_wT3[0][0]);
    const float* Xb = (LAYER == 0) ? &d_g[b][0][0] : (LAYER == 1 ? &d_y1[b][0][0] : &d_y2[b][0][0]);

    int r0 = tid >> 4;                   // load rows r0, r0+16
    int c4 = (tid & 15) * 4;             // load col base

    float4 ra[2], rb[2];
    ra[0] = *(const float4*)&Wt[r0 * M + m0 + c4];
    ra[1] = *(const float4*)&Wt[(r0 + 16) * M + m0 + c4];
    rb[0] = *(const float4*)&Xb[(size_t)r0 * NS + n0 + c4];
    rb[1] = *(const float4*)&Xb[(size_t)(r0 + 16) * NS + n0 + c4];

    for (int k0 = 0; k0 < K; k0 += KT) {
        *(float4*)&As[r0][c4]      = ra[0];
        *(float4*)&As[r0 + 16][c4] = ra[1];
        if (LAYER > 0) {
            #pragma unroll
            for (int j = 0; j < 2; j++) {
                float a = s_scale[k0 + r0 + 16 * j], h = s_shift[k0 + r0 + 16 * j];
                rb[j].x = fmaxf(fmaf(a, rb[j].x, h), 0.f);
                rb[j].y = fmaxf(fmaf(a, rb[j].y, h), 0.f);
                rb[j].z = fmaxf(fmaf(a, rb[j].z, h), 0.f);
                rb[j].w = fmaxf(fmaf(a, rb[j].w, h), 0.f);
            }
        }
        *(float4*)&Bs[r0][c4]      = rb[0];
        *(float4*)&Bs[r0 + 16][c4] = rb[1];
        __syncthreads();

        if (k0 + KT < K) {
            int kn = k0 + KT;
            ra[0] = *(const float4*)&Wt[(kn + r0) * M + m0 + c4];
            ra[1] = *(const float4*)&Wt[(kn + r0 + 16) * M + m0 + c4];
            rb[0] = *(const float4*)&Xb[(size_t)(kn + r0) * NS + n0 + c4];
            rb[1] = *(const float4*)&Xb[(size_t)(kn + r0 + 16) * NS + n0 + c4];
        }

        #pragma unroll
        for (int kk = 0; kk < KT; kk++) {
            float4 a0 = *(float4*)&As[kk][tm];
            float4 bb = *(float4*)&Bs[kk][tn];
            unsigned long long b01 = pk2(bb.x, bb.y);
            unsigned long long b23 = pk2(bb.z, bb.w);
            unsigned long long aa;
            aa = pk2(a0.x, a0.x); FFMA2(acc2[0][0], aa, b01); FFMA2(acc2[0][1], aa, b23);
            aa = pk2(a0.y, a0.y); FFMA2(acc2[1][0], aa, b01); FFMA2(acc2[1][1], aa, b23);
            aa = pk2(a0.z, a0.z); FFMA2(acc2[2][0], aa, b01); FFMA2(acc2[2][1], aa, b23);
            aa = pk2(a0.w, a0.w); FFMA2(acc2[3][0], aa, b01); FFMA2(acc2[3][1], aa, b23);
        }
        __syncthreads();
    }

    float acc[4][4];
    #pragma unroll
    for (int i = 0; i < 4; i++) {
        unpk2(acc2[i][0], acc[i][0], acc[i][1]);
        unpk2(acc2[i][1], acc[i][2], acc[i][3]);
    }

    // epilogue
    float* Yb = (LAYER == 0) ? &d_y1[b][0][0] : &d_y2[b][0][0];
    float rmax[4], rmin[4];
    #pragma unroll
    for (int i = 0; i < 4; i++) {
        float bi = bias[m0 + tm + i];
        float s = 0.f, s2 = 0.f, mx = -3.0e38f, mnv = 3.0e38f;
        #pragma unroll
        for (int j = 0; j < 4; j++) {
            float v = acc[i][j] + bi;
            acc[i][j] = v;
            s += v; s2 += v * v;
            mx = fmaxf(mx, v); mnv = fminf(mnv, v);
        }
        if (LAYER < 2)
            *(float4*)&Yb[(size_t)(m0 + tm + i) * NS + n0 + tn] =
                make_float4(acc[i][0], acc[i][1], acc[i][2], acc[i][3]);
        red [g][tm + i] = s;
        red2[g][tm + i] = s2;
        rmax[i] = mx; rmin[i] = mnv;
    }
    __syncthreads();
    if (tid < MH) {
        float s = 0.f, s2 = 0.f;
        #pragma unroll
        for (int gg = 0; gg < 16; gg++) { s += red[gg][tid]; s2 += red2[gg][tid]; }
        atomicAdd(&d_sum [LAYER][m0 + tid], s);
        atomicAdd(&d_sum2[LAYER][m0 + tid], s2);
    }
    if (LAYER == 2) {
        __syncthreads();
        #pragma unroll
        for (int i = 0; i < 4; i++) { red[g][tm + i] = rmax[i]; red2[g][tm + i] = rmin[i]; }
        __syncthreads();
        if (tid < MH) {
            float mx = -3.0e38f, mnv = 3.0e38f;
            #pragma unroll
            for (int gg = 0; gg < 16; gg++) { mx = fmaxf(mx, red[gg][tid]); mnv = fminf(mnv, red2[gg][tid]); }
            atomicMax(&d_maxenc[b][m0 + tid], enc(mx));
            atomicMin(&d_minenc[b][m0 + tid], enc(mnv));
        }
    }
}

// ---------------- 3) FC head (1024 thr; transposed weights) ----------------
__global__ void __launch_bounds__(1024)
head_kernel(const float* __restrict__ xyz,
            const float* __restrict__ g3,  const float* __restrict__ be3,
            const float* __restrict__ hb1,
            const float* __restrict__ hg1, const float* __restrict__ hbe1,
            const float* __restrict__ hb2,
            const float* __restrict__ hg2, const float* __restrict__ hbe2,
            const float* __restrict__ hw3, const float* __restrict__ hb3,
            float* __restrict__ out) {
    __shared__ float sf[B][M];
    __shared__ float z [B][M];
    __shared__ float sa[M], sb_[M];
    int tid = threadIdx.x;          // 1024
    int b = tid >> 7, o = tid & 127;

    if (tid < M) {
        float inv = 1.0f / (float)(B * NS);
        float mn  = d_sum [2][tid] * inv;
        float var = d_sum2[2][tid] * inv - mn * mn;
        float a = g3[tid] * rsqrtf(var + EPS);
        sa[tid] = a;
        sb_[tid] = be3[tid] - mn * a;
    }
    __syncthreads();
    {
        float a = sa[o], d = sb_[o];
        float mx = dec(d_maxenc[b][o]);
        float mnv = dec(d_minenc[b][o]);
        float v = (a >= 0.f) ? fmaf(a, mx, d) : fmaf(a, mnv, d);
        sf[b][o] = fmaxf(v, 0.f);
    }
    __syncthreads();

    // layer 1
    {
        float acc = hb1[o];
        #pragma unroll 16
        for (int k = 0; k < M; k++) acc = fmaf(sf[b][k], d_hT1[k][o], acc);
        z[b][o] = acc;
    }
    __syncthreads();
    if (tid < M) {
        float s = 0.f, s2 = 0.f;
        for (int bb = 0; bb < B; bb++) { float v = z[bb][tid]; s += v; s2 += v * v; }
        float mn = s * 0.125f, var = s2 * 0.125f - mn * mn;
        float a = hg1[tid] * rsqrtf(var + EPS);
        sa[tid] = a; sb_[tid] = hbe1[tid] - mn * a;
    }
    __syncthreads();
    sf[b][o] = fmaxf(fmaf(sa[o], z[b][o], sb_[o]), 0.f);
    __syncthreads();

    // layer 2
    {
        float acc = hb2[o];
        #pragma unroll 16
        for (int k = 0; k < M; k++) acc = fmaf(sf[b][k], d_hT2[k][o], acc);
        z[b][o] = acc;
    }
    __syncthreads();
    if (tid < M) {
        float s = 0.f, s2 = 0.f;
        for (int bb = 0; bb < B; bb++) { float v = z[bb][tid]; s += v; s2 += v * v; }
        float mn = s * 0.125f, var = s2 * 0.125f - mn * mn;
        float a = hg2[tid] * rsqrtf(var + EPS);
        sa[tid] = a; sb_[tid] = hbe2[tid] - mn * a;
    }
    __syncthreads();
    sf[b][o] = fmaxf(fmaf(sa[o], z[b][o], sb_[o]), 0.f);
    __syncthreads();

    // layer 3: 8 x 12 outputs
    if (tid < B * 12) {
        int bb = tid / 12, oo = tid % 12;
        float acc = hb3[oo];
        #pragma unroll 16
        for (int k = 0; k < M; k++) acc = fmaf(sf[bb][k], hw3[oo * M + k], acc);
        if (oo < 3)      out[bb * 3 + oo]            = xyz[(size_t)bb * N * 3 + oo] + acc;
        else if (oo < 6) out[24 + bb * 3 + (oo - 3)] = acc;
        else             out[48 + bb * 6 + (oo - 6)] = acc;
    }
}

// ---------------- launch ---------------------------------------------------
extern "C" void kernel_launch(void* const* d_in, const int* in_sizes, int n_in,
                              void* d_out, int out_size) {
    const float* xyz  = (const float*)d_in[0];
    const float* feat = (const float*)d_in[1];
    const float* w1   = (const float*)d_in[2];
    const float* b1   = (const float*)d_in[3];
    const float* g1   = (const float*)d_in[4];
    const float* be1  = (const float*)d_in[5];
    const float* w2   = (const float*)d_in[6];
    const float* b2   = (const float*)d_in[7];
    const float* g2   = (const float*)d_in[8];
    const float* be2  = (const float*)d_in[9];
    const float* w3   = (const float*)d_in[10];
    const float* b3   = (const float*)d_in[11];
    const float* g3   = (const float*)d_in[12];
    const float* be3  = (const float*)d_in[13];
    const float* hw1  = (const float*)d_in[14];
    const float* hb1  = (const float*)d_in[15];
    const float* hg1  = (const float*)d_in[16];
    const float* hbe1 = (const float*)d_in[17];
    const float* hw2  = (const float*)d_in[18];
    const float* hb2  = (const float*)d_in[19];
    const float* hg2  = (const float*)d_in[20];
    const float* hbe2 = (const float*)d_in[21];
    const float* hw3  = (const float*)d_in[22];
    const float* hb3  = (const float*)d_in[23];
    float* out = (float*)d_out;

    setup_kernel<<<B, 256>>>(xyz);
    gather_kernel<<<dim3(C + 2, B), 128>>>(feat, w1, w2, w3, hw1, hw2);

    dim3 gemm_grid(NS / NT, M / MH, B);      // (16, 2, 8) = 256 blocks
    gemm_kernel<KP, 0><<<gemm_grid, 256>>>(b1, nullptr, nullptr);
    gemm_kernel<M,  1><<<gemm_grid, 256>>>(b2, g1, be1);
    gemm_kernel<M,  2><<<gemm_grid, 256>>>(b3, g2, be2);

    head_kernel<<<1, 1024>>>(xyz, g3, be3,
                             hb1, hg1, hbe1,
                             hb2, hg2, hbe2, hw3, hb3, out);
}